// round 15
// baseline (speedup 1.0000x reference)
#include <cuda_runtime.h>
#include <math.h>

typedef unsigned long long ull;

// ---------------------------------------------------------------------------
// Scratch buffers (device globals; no allocation anywhere)
// ---------------------------------------------------------------------------
__device__ float g_buf1[33554432];  // 32x64x128x128 (h1, later deconv1 out)
__device__ float g_buf2[16777216];  // 32x128x64x64
__device__ float g_buf3[16777216];  // 32x128x64x64 (enc res state)
__device__ float g_buf4[4194304];   // 32x32x64x64  (res hidden)
__device__ float g_z[8388608];      // 32x64x64x64
__device__ float g_q[8388608];      // 32x64x64x64
__device__ float g_d[16777216];     // 32x128x64x64 (dec res state)
__device__ float g_enorm[512];
__device__ float g_bsum[1024];

// ---------------------------------------------------------------------------
// Packed dual-fp32 helpers (FFMA2 via PTX fma.rn.f32x2; bit-identical to two
// scalar fmaf)
// ---------------------------------------------------------------------------
__device__ __forceinline__ ull pack2(float v) {
    ull p;
    asm("mov.b64 %0, {%1, %1};" : "=l"(p) : "f"(v));
    return p;
}
__device__ __forceinline__ void ffma2(ull& d, ull a, ull b) {
    asm("fma.rn.f32x2 %0, %1, %2, %0;" : "+l"(d) : "l"(a), "l"(b));
}
__device__ __forceinline__ float2 unpack2(ull p) {
    float2 r;
    asm("mov.b64 {%0, %1}, %2;" : "=f"(r.x), "=f"(r.y) : "l"(p));
    return r;
}
template<int NP>
__device__ __forceinline__ void load_w128(ull* wv, const float* p) {
    const ulonglong2* wq = reinterpret_cast<const ulonglong2*>(p);
    #pragma unroll
    for (int i = 0; i < NP / 2; i++) {
        ulonglong2 t = wq[i];
        wv[2 * i]     = t.x;
        wv[2 * i + 1] = t.y;
    }
}

// ---------------------------------------------------------------------------
// cp.async helpers
// ---------------------------------------------------------------------------
__device__ __forceinline__ void cp_async16(unsigned saddr, const void* g, bool valid) {
    int sz = valid ? 16 : 0;
    asm volatile("cp.async.cg.shared.global [%0], [%1], 16, %2;\n"
                 :: "r"(saddr), "l"(g), "r"(sz));
}
__device__ __forceinline__ void cp_async4(unsigned saddr, const void* g) {
    asm volatile("cp.async.ca.shared.global [%0], [%1], 4;\n"
                 :: "r"(saddr), "l"(g));
}
__device__ __forceinline__ void cp_commit() {
    asm volatile("cp.async.commit_group;\n" ::: "memory");
}
template<int N>
__device__ __forceinline__ void cp_wait() {
    asm volatile("cp.async.wait_group %0;\n" :: "n"(N) : "memory");
}

// ---------------------------------------------------------------------------
// 3x3 s1 p1 conv, 16B-cp.async double-buffered (the measured-220us kernel).
// 16x16 out tile, 64 threads (8x8), 2x2 outputs x OCB oc per thread.
// in_relu: relu applied in REGISTERS at pack time (math identical to a
// loader-side relu; OOB zfill zeros unaffected).
// Accumulation order: chunk -> ci -> kh -> kw (bit-identical to generic).
// Requires Cin % CB == 0, Win % 4 == 0.
// ---------------------------------------------------------------------------
template<int OCB, int CB>
__global__ void __launch_bounds__(64) conv3x3_async_kernel(
    const float* __restrict__ in, const float* __restrict__ w,
    const float* __restrict__ bias,
    float* __restrict__ out,
    int Cin, int Hin, int Win, int Cout, int in_relu, int act)
{
    constexpr int TILE = 16;
    constexpr int ITY = 18, ITX = 24;
    constexpr int NP = OCB / 2;
    constexpr int IN_CHUNKS = CB * ITY * (ITX / 4);
    constexpr int W_ELE = CB * 9 * OCB;
    __shared__ __align__(16) float s_in[2][CB * ITY * ITX];
    __shared__ __align__(16) float s_w[2][W_ELE];

    const int Hout = Hin, Wout = Win;
    const int groups = Cout / OCB;
    const int n   = blockIdx.z / groups;
    const int oc0 = (blockIdx.z % groups) * OCB;
    const int ox0 = blockIdx.x * TILE;
    const int oy0 = blockIdx.y * TILE;
    const int tx = threadIdx.x, ty = threadIdx.y;   // 8x8
    const int tid = ty * 8 + tx;

    ull acc[2][2][NP];
    #pragma unroll
    for (int a = 0; a < 2; a++)
        #pragma unroll
        for (int b = 0; b < 2; b++)
            #pragma unroll
            for (int p = 0; p < NP; p++) acc[a][b][p] = 0ULL;

    const int iy0 = oy0 - 1;
    const int ix4 = ox0 - 4;          // 16B-aligned tile base
    const int nch = Cin / CB;

    auto load_stage = [&](int st, int c0) {
        unsigned sin = (unsigned)__cvta_generic_to_shared(&s_in[st][0]);
        for (int idx = tid; idx < IN_CHUNKS; idx += 64) {
            int ci  = idx / (ITY * 6);
            int r   = idx - ci * (ITY * 6);
            int row = r / 6, q = r - row * 6;
            int gy = iy0 + row;
            int gx = ix4 + q * 4;
            bool v = (gy >= 0 && gy < Hin && gx >= 0 && gx < Win);
            const float* gp = &in[((size_t)(n * Cin + c0 + ci) * Hin + (v ? gy : 0)) * Win
                                  + (v ? gx : 0)];
            cp_async16(sin + idx * 16, gp, v);
        }
        unsigned sw = (unsigned)__cvta_generic_to_shared(&s_w[st][0]);
        for (int idx = tid; idx < W_ELE; idx += 64) {
            int o  = idx % OCB;
            int r  = idx / OCB;
            int ci = r / 9;
            int kk = r - ci * 9;
            cp_async4(sw + idx * 4, &w[((size_t)(oc0 + o) * Cin + c0 + ci) * 9 + kk]);
        }
    };

    load_stage(0, 0);
    cp_commit();

    for (int ch = 0; ch < nch; ch++) {
        if (ch + 1 < nch) load_stage((ch + 1) & 1, (ch + 1) * CB);
        cp_commit();
        cp_wait<1>();
        __syncthreads();

        const int st = ch & 1;
        for (int ci = 0; ci < CB; ci++) {
            #pragma unroll
            for (int kh = 0; kh < 3; kh++) {
                // span cols tx*2+2 .. tx*2+7 (8B-aligned base); needed tmp[1..4]
                ull pk[2][4];
                #pragma unroll
                for (int dy = 0; dy < 2; dy++) {
                    const float2* rp = reinterpret_cast<const float2*>(
                        &s_in[st][(ci * ITY + ty * 2 + dy + kh) * ITX + tx * 2 + 2]);
                    float2 v0 = rp[0], v1 = rp[1], v2 = rp[2];
                    float a0 = v0.y, a1 = v1.x, a2 = v1.y, a3 = v2.x;
                    if (in_relu) {
                        a0 = fmaxf(a0, 0.f); a1 = fmaxf(a1, 0.f);
                        a2 = fmaxf(a2, 0.f); a3 = fmaxf(a3, 0.f);
                    }
                    pk[dy][0] = pack2(a0);
                    pk[dy][1] = pack2(a1);
                    pk[dy][2] = pack2(a2);
                    pk[dy][3] = pack2(a3);
                }
                #pragma unroll
                for (int kw = 0; kw < 3; kw++) {
                    ull wv[NP];
                    load_w128<NP>(wv, &s_w[st][(ci * 9 + kh * 3 + kw) * OCB]);
                    #pragma unroll
                    for (int dy = 0; dy < 2; dy++) {
                        #pragma unroll
                        for (int dx = 0; dx < 2; dx++) {
                            #pragma unroll
                            for (int p = 0; p < NP; p++)
                                ffma2(acc[dy][dx][p], pk[dy][dx + kw], wv[p]);
                        }
                    }
                }
            }
        }
        __syncthreads();
    }

    #pragma unroll
    for (int dy = 0; dy < 2; dy++) {
        int oy = oy0 + ty * 2 + dy;
        if (oy >= Hout) continue;
        #pragma unroll
        for (int dx = 0; dx < 2; dx++) {
            int ox = ox0 + tx * 2 + dx;
            if (ox >= Wout) continue;
            #pragma unroll
            for (int p = 0; p < NP; p++) {
                float2 r2 = unpack2(acc[dy][dx][p]);
                #pragma unroll
                for (int h = 0; h < 2; h++) {
                    int o = 2 * p + h;
                    float v = (h ? r2.y : r2.x) + bias[oc0 + o];
                    int oidx = ((n * Cout + oc0 + o) * Hout + oy) * Wout + ox;
                    if (act == 1) v = fmaxf(v, 0.f);
                    out[oidx] = v;
                }
            }
        }
    }
}

// ---------------------------------------------------------------------------
// Generic direct conv (R10 verbatim): 16x16 out tile, 64 threads,
// 2x2 outputs x OCB oc per thread.
// ---------------------------------------------------------------------------
template<int K, int S, int OCB, int CB>
__global__ void __launch_bounds__(64) conv2d_kernel(
    const float* __restrict__ in, const float* __restrict__ w,
    const float* __restrict__ bias, const float* __restrict__ resid,
    float* __restrict__ out,
    int Cin, int Hin, int Win, int Cout, int Hout, int Wout,
    int pad, int in_relu, int act)
{
    constexpr int TILE = 16;
    constexpr int IT = TILE * S + K - S;
    constexpr int NP = OCB / 2;
    constexpr int SPAN = S + K;
    __shared__ __align__(16) float s_in[CB * IT * IT];
    __shared__ __align__(16) float s_w[CB * K * K * OCB];

    const int groups = Cout / OCB;
    const int n   = blockIdx.z / groups;
    const int oc0 = (blockIdx.z % groups) * OCB;
    const int ox0 = blockIdx.x * TILE;
    const int oy0 = blockIdx.y * TILE;
    const int tx = threadIdx.x, ty = threadIdx.y;
    const int tid = ty * 8 + tx;

    ull acc[2][2][NP];
    #pragma unroll
    for (int a = 0; a < 2; a++)
        #pragma unroll
        for (int b = 0; b < 2; b++)
            #pragma unroll
            for (int p = 0; p < NP; p++) acc[a][b][p] = 0ULL;

    const int ix0 = ox0 * S - pad;
    const int iy0 = oy0 * S - pad;

    for (int c0 = 0; c0 < Cin; c0 += CB) {
        const int cb = min(CB, Cin - c0);

        for (int idx = tid; idx < cb * IT * IT; idx += 64) {
            int ci = idx / (IT * IT);
            int r  = idx - ci * IT * IT;
            int iy = r / IT, ix = r - iy * IT;
            int gy = iy0 + iy, gx = ix0 + ix;
            float v = 0.f;
            if (gy >= 0 && gy < Hin && gx >= 0 && gx < Win)
                v = in[((n * Cin + c0 + ci) * Hin + gy) * Win + gx];
            if (in_relu) v = fmaxf(v, 0.f);
            s_in[idx] = v;
        }
        for (int idx = tid; idx < cb * K * K * OCB; idx += 64) {
            int o  = idx % OCB;
            int r  = idx / OCB;
            int ci = r / (K * K);
            int kk = r - ci * (K * K);
            s_w[idx] = w[((oc0 + o) * Cin + c0 + ci) * (K * K) + kk];
        }
        __syncthreads();

        for (int ci = 0; ci < cb; ci++) {
            #pragma unroll
            for (int kh = 0; kh < K; kh++) {
                ull pk[2][SPAN];
                #pragma unroll
                for (int dy = 0; dy < 2; dy++) {
                    const float2* rp = reinterpret_cast<const float2*>(
                        &s_in[(ci * IT + (ty * 2 + dy) * S + kh) * IT + tx * 2 * S]);
                    float tmp[SPAN];
                    #pragma unroll
                    for (int i = 0; i < SPAN / 2; i++) {
                        float2 v2 = rp[i];
                        tmp[2 * i]     = v2.x;
                        tmp[2 * i + 1] = v2.y;
                    }
                    #pragma unroll
                    for (int i = 0; i < SPAN; i++) pk[dy][i] = pack2(tmp[i]);
                }
                #pragma unroll
                for (int kw = 0; kw < K; kw++) {
                    ull wv[NP];
                    load_w128<NP>(wv, &s_w[((ci * K + kh) * K + kw) * OCB]);
                    #pragma unroll
                    for (int dy = 0; dy < 2; dy++) {
                        #pragma unroll
                        for (int dx = 0; dx < 2; dx++) {
                            #pragma unroll
                            for (int p = 0; p < NP; p++)
                                ffma2(acc[dy][dx][p], pk[dy][dx * S + kw], wv[p]);
                        }
                    }
                }
            }
        }
        __syncthreads();
    }

    #pragma unroll
    for (int dy = 0; dy < 2; dy++) {
        int oy = oy0 + ty * 2 + dy;
        if (oy >= Hout) continue;
        #pragma unroll
        for (int dx = 0; dx < 2; dx++) {
            int ox = ox0 + tx * 2 + dx;
            if (ox >= Wout) continue;
            #pragma unroll
            for (int p = 0; p < NP; p++) {
                float2 r2 = unpack2(acc[dy][dx][p]);
                #pragma unroll
                for (int h = 0; h < 2; h++) {
                    int o = 2 * p + h;
                    float v = (h ? r2.y : r2.x) + bias[oc0 + o];
                    int oidx = ((n * Cout + oc0 + o) * Hout + oy) * Wout + ox;
                    if (resid) v += resid[oidx];
                    if (act == 1)      v = fmaxf(v, 0.f);
                    else if (act == 2) v = tanhf(v);
                    out[oidx] = v;
                }
            }
        }
    }
}

// ---------------------------------------------------------------------------
// ConvTranspose2d(k=4, s=2, p=1): R10 verbatim.
// ---------------------------------------------------------------------------
template<int COB, int CB>
__global__ void __launch_bounds__(128) deconv_k4s2_kernel(
    const float* __restrict__ in, const float* __restrict__ w,
    const float* __restrict__ bias, float* __restrict__ out,
    int Cin, int Hin, int Win, int Cout, int act)
{
    constexpr int NP = COB / 2;
    __shared__ __align__(16) float s_in[CB * 18 * 18];
    __shared__ __align__(16) float s_w[CB * 16 * COB];

    const int Hout = Hin * 2, Wout = Win * 2;
    const int groups = (Cout + COB - 1) / COB;
    const int n   = blockIdx.z / groups;
    const int co0 = (blockIdx.z % groups) * COB;
    const int uw0 = blockIdx.x * 16, uh0 = blockIdx.y * 16;
    const int tx = threadIdx.x, ty = threadIdx.y;   // 8x16
    const int tid = ty * 8 + tx;

    ull acc[2][2][2][NP];
    #pragma unroll
    for (int j = 0; j < 2; j++)
        #pragma unroll
        for (int py = 0; py < 2; py++)
            #pragma unroll
            for (int px = 0; px < 2; px++)
                #pragma unroll
                for (int p = 0; p < NP; p++) acc[j][py][px][p] = 0ULL;

    for (int c0 = 0; c0 < Cin; c0 += CB) {
        const int cb = min(CB, Cin - c0);
        for (int idx = tid; idx < cb * 324; idx += 128) {
            int ci = idx / 324;
            int r  = idx - ci * 324;
            int iy = r / 18, ix = r - iy * 18;
            int gy = uh0 - 1 + iy, gx = uw0 - 1 + ix;
            float v = 0.f;
            if (gy >= 0 && gy < Hin && gx >= 0 && gx < Win)
                v = in[((n * Cin + c0 + ci) * Hin + gy) * Win + gx];
            s_in[idx] = v;
        }
        for (int idx = tid; idx < cb * 16 * COB; idx += 128) {
            int o  = idx % COB;
            int r  = idx / COB;
            int ci = r / 16;
            int kk = r - ci * 16;
            float v = 0.f;
            if (co0 + o < Cout)
                v = w[((c0 + ci) * Cout + co0 + o) * 16 + kk];
            s_w[idx] = v;
        }
        __syncthreads();

        for (int ci = 0; ci < cb; ci++) {
            ull pk[3][4];
            #pragma unroll
            for (int r = 0; r < 3; r++) {
                const float2* rp = reinterpret_cast<const float2*>(
                    &s_in[(ci * 18 + ty + r) * 18 + tx * 2]);
                float2 a = rp[0], b = rp[1];
                pk[r][0] = pack2(a.x); pk[r][1] = pack2(a.y);
                pk[r][2] = pack2(b.x); pk[r][3] = pack2(b.y);
            }
            #pragma unroll
            for (int kh = 0; kh < 4; kh++) {
                const int py = (kh + 1) & 1;
                const int ro = (kh == 0) ? 2 : ((kh == 3) ? 0 : 1);
                #pragma unroll
                for (int kw = 0; kw < 4; kw++) {
                    const int px = (kw + 1) & 1;
                    const int co = (kw == 0) ? 2 : ((kw == 3) ? 0 : 1);
                    ull wv[NP];
                    load_w128<NP>(wv, &s_w[(ci * 16 + kh * 4 + kw) * COB]);
                    #pragma unroll
                    for (int j = 0; j < 2; j++) {
                        #pragma unroll
                        for (int p = 0; p < NP; p++)
                            ffma2(acc[j][py][px][p], pk[ro][j + co], wv[p]);
                    }
                }
            }
        }
        __syncthreads();
    }

    #pragma unroll
    for (int j = 0; j < 2; j++) {
        #pragma unroll
        for (int py = 0; py < 2; py++) {
            int oy = 2 * (uh0 + ty) + py;
            #pragma unroll
            for (int px = 0; px < 2; px++) {
                int ox = 2 * (uw0 + tx * 2 + j) + px;
                #pragma unroll
                for (int p = 0; p < NP; p++) {
                    float2 r2 = unpack2(acc[j][py][px][p]);
                    #pragma unroll
                    for (int h = 0; h < 2; h++) {
                        int o = 2 * p + h;
                        if (co0 + o < Cout) {
                            float v = (h ? r2.y : r2.x) + bias[co0 + o];
                            if (act == 1)      v = fmaxf(v, 0.f);
                            else if (act == 2) v = tanhf(v);
                            out[((n * Cout + co0 + o) * Hout + oy) * Wout + ox] = v;
                        }
                    }
                }
            }
        }
    }
}

// ---------------------------------------------------------------------------
// VQ kernels (R10 verbatim)
// ---------------------------------------------------------------------------
__global__ void vq_prep_kernel(const float* __restrict__ cb, float* __restrict__ enorm)
{
    int k = blockIdx.x * blockDim.x + threadIdx.x;
    if (k < 512) {
        float s = 0.f;
        #pragma unroll
        for (int d = 0; d < 64; d++) { float v = cb[k * 64 + d]; s += v * v; }
        enorm[k] = s;
    }
}

__global__ void __launch_bounds__(128) vq_kernel(
    const float* __restrict__ z, const float* __restrict__ cb,
    const float* __restrict__ enorm, float* __restrict__ q,
    float* __restrict__ bsum)
{
    __shared__ __align__(16) float sc[64 * 66];
    __shared__ float se[64];
    __shared__ float sred[128];

    const int tid = threadIdx.x;
    const int v   = blockIdx.x * 128 + tid;
    const int b   = v >> 12;
    const int hw  = v & 4095;

    const float* zp = z + b * 64 * 4096 + hw;
    float zr[64];
    float znorm = 0.f;
    #pragma unroll
    for (int d = 0; d < 64; d++) { zr[d] = zp[d * 4096]; znorm += zr[d] * zr[d]; }

    float best = 3.402823e38f;
    int   bi   = 0;
    for (int c0 = 0; c0 < 512; c0 += 64) {
        __syncthreads();
        for (int i = tid; i < 4096; i += 128) {
            int c = i >> 6, d = i & 63;
            sc[d * 66 + c] = cb[(c0 + c) * 64 + d];
        }
        if (tid < 64) se[tid] = enorm[c0 + tid];
        __syncthreads();
        #pragma unroll
        for (int g = 0; g < 4; g++) {
            ull dp[8];
            #pragma unroll
            for (int p = 0; p < 8; p++) dp[p] = 0ULL;
            #pragma unroll
            for (int d = 0; d < 64; d++) {
                ull z2 = pack2(zr[d]);
                const ull* row = (const ull*)&sc[d * 66 + g * 16];
                #pragma unroll
                for (int p = 0; p < 8; p++) ffma2(dp[p], z2, row[p]);
            }
            #pragma unroll
            for (int p = 0; p < 8; p++) {
                float2 dd = unpack2(dp[p]);
                int c = g * 16 + 2 * p;
                float dist0 = znorm - 2.f * dd.x + se[c];
                if (dist0 < best) { best = dist0; bi = c0 + c; }
                float dist1 = znorm - 2.f * dd.y + se[c + 1];
                if (dist1 < best) { best = dist1; bi = c0 + c + 1; }
            }
        }
    }

    const float* e = cb + bi * 64;
    float* qp = q + b * 64 * 4096 + hw;
    float err = 0.f;
    #pragma unroll
    for (int d = 0; d < 64; d++) {
        float ev = e[d];
        float df = ev - zr[d];
        err += df * df;
        qp[d * 4096] = ev;
    }

    sred[tid] = err;
    __syncthreads();
    for (int s = 64; s > 0; s >>= 1) {
        if (tid < s) sred[tid] += sred[tid + s];
        __syncthreads();
    }
    if (tid == 0) bsum[blockIdx.x] = sred[0];
}

__global__ void finalize_kernel(const float* __restrict__ bsum, float* __restrict__ out_loss)
{
    __shared__ float s[256];
    int t = threadIdx.x;
    float v = 0.f;
    for (int i = t; i < 1024; i += 256) v += bsum[i];
    s[t] = v;
    __syncthreads();
    for (int k = 128; k > 0; k >>= 1) {
        if (t < k) s[t] += s[t + k];
        __syncthreads();
    }
    if (t == 0) out_loss[0] = 1.25f * s[0] / 8388608.0f;
}

// ---------------------------------------------------------------------------
// Launcher (R10 geometry; res 3x3 layers swapped to the async kernel)
// ---------------------------------------------------------------------------
extern "C" void kernel_launch(void* const* d_in, const int* in_sizes, int n_in,
                              void* d_out, int out_size)
{
    const float* x        = (const float*)d_in[0];
    const float* enc_w1   = (const float*)d_in[1];
    const float* enc_b1   = (const float*)d_in[2];
    const float* enc_w2   = (const float*)d_in[3];
    const float* enc_b2   = (const float*)d_in[4];
    const float* enc_w3   = (const float*)d_in[5];
    const float* enc_b3   = (const float*)d_in[6];
    const float* enc_rw1  = (const float*)d_in[7];
    const float* enc_rb1  = (const float*)d_in[8];
    const float* enc_rw2  = (const float*)d_in[9];
    const float* enc_rb2  = (const float*)d_in[10];
    const float* pvq_w    = (const float*)d_in[11];
    const float* pvq_b    = (const float*)d_in[12];
    const float* codebook = (const float*)d_in[13];
    const float* dec_w1   = (const float*)d_in[14];
    const float* dec_b1   = (const float*)d_in[15];
    const float* dec_rw1  = (const float*)d_in[16];
    const float* dec_rb1  = (const float*)d_in[17];
    const float* dec_rw2  = (const float*)d_in[18];
    const float* dec_rb2  = (const float*)d_in[19];
    const float* dt1_w    = (const float*)d_in[20];
    const float* dt1_b    = (const float*)d_in[21];
    const float* dt2_w    = (const float*)d_in[22];
    const float* dt2_b    = (const float*)d_in[23];
    float* outp = (float*)d_out;

    static float *b1 = nullptr, *b2, *b3, *b4, *bz, *bq, *bd, *pe, *pbs;
    if (!b1) {
        cudaGetSymbolAddress((void**)&b1,  g_buf1);
        cudaGetSymbolAddress((void**)&b2,  g_buf2);
        cudaGetSymbolAddress((void**)&b3,  g_buf3);
        cudaGetSymbolAddress((void**)&b4,  g_buf4);
        cudaGetSymbolAddress((void**)&bz,  g_z);
        cudaGetSymbolAddress((void**)&bq,  g_q);
        cudaGetSymbolAddress((void**)&bd,  g_d);
        cudaGetSymbolAddress((void**)&pe,  g_enorm);
        cudaGetSymbolAddress((void**)&pbs, g_bsum);
    }

    const dim3 blk(8, 8);      // 64 threads, 16x16 output tile
    const dim3 dblk(8, 16);
    const int N = 32;

    // ---- Encoder ----
    // conv1: 3->64, k4 s2 p1, relu  (256 -> 128)
    conv2d_kernel<4, 2, 16, 4><<<dim3(8, 8, N * (64 / 16)), blk>>>(
        x, enc_w1, enc_b1, nullptr, b1, 3, 256, 256, 64, 128, 128, 1, 0, 1);
    // conv2: 64->128, k4 s2 p1, relu  (128 -> 64)
    conv2d_kernel<4, 2, 16, 4><<<dim3(4, 4, N * (128 / 16)), blk>>>(
        b1, enc_w2, enc_b2, nullptr, b2, 64, 128, 128, 128, 64, 64, 1, 0, 1);
    // conv3: 128->128, k3 s1 p1, no act  (R10 generic)
    conv2d_kernel<3, 1, 16, 8><<<dim3(4, 4, N * (128 / 16)), blk>>>(
        b2, enc_w3, enc_b3, nullptr, b3, 128, 64, 64, 128, 64, 64, 1, 0, 0);
    // residual stack x2: 3x3 via async kernel (in-pack relu), 1x1 R10 generic
    for (int i = 0; i < 2; i++) {
        const float* w1p = enc_rw1 + (size_t)i * 32 * 128 * 9;
        const float* b1p = enc_rb1 + i * 32;
        const float* w2p = enc_rw2 + (size_t)i * 128 * 32;
        const float* b2p = enc_rb2 + i * 128;
        conv3x3_async_kernel<8, 8><<<dim3(4, 4, N * (32 / 8)), blk>>>(
            b3, w1p, b1p, b4, 128, 64, 64, 32, 1, 0);
        conv2d_kernel<1, 1, 16, 16><<<dim3(4, 4, N * (128 / 16)), blk>>>(
            b4, w2p, b2p, b3, b3, 32, 64, 64, 128, 64, 64, 0, 1, (i == 1) ? 1 : 0);
    }
    // pre-VQ 1x1: 128->64
    conv2d_kernel<1, 1, 16, 16><<<dim3(4, 4, N * (64 / 16)), blk>>>(
        b3, pvq_w, pvq_b, nullptr, bz, 128, 64, 64, 64, 64, 64, 0, 0, 0);

    // ---- VQ ----
    vq_prep_kernel<<<2, 256>>>(codebook, pe);
    vq_kernel<<<1024, 128>>>(bz, codebook, pe, bq, pbs);

    // ---- Decoder ----
    // dec conv1: 64->128, k3 s1 p1, no act  (R10 generic)
    conv2d_kernel<3, 1, 16, 8><<<dim3(4, 4, N * (128 / 16)), blk>>>(
        bq, dec_w1, dec_b1, nullptr, bd, 64, 64, 64, 128, 64, 64, 1, 0, 0);
    // residual stack x2
    for (int i = 0; i < 2; i++) {
        const float* w1p = dec_rw1 + (size_t)i * 32 * 128 * 9;
        const float* b1p = dec_rb1 + i * 32;
        const float* w2p = dec_rw2 + (size_t)i * 128 * 32;
        const float* b2p = dec_rb2 + i * 128;
        conv3x3_async_kernel<8, 8><<<dim3(4, 4, N * (32 / 8)), blk>>>(
            bd, w1p, b1p, b4, 128, 64, 64, 32, 1, 0);
        conv2d_kernel<1, 1, 16, 16><<<dim3(4, 4, N * (128 / 16)), blk>>>(
            b4, w2p, b2p, bd, bd, 32, 64, 64, 128, 64, 64, 0, 1, (i == 1) ? 1 : 0);
    }
    // deconv1: 128->64, relu  (64 -> 128)
    deconv_k4s2_kernel<8, 8><<<dim3(4, 4, N * (64 / 8)), dblk>>>(
        bd, dt1_w, dt1_b, b1, 128, 64, 64, 64, 1);
    // deconv2: 64->3, tanh  (128 -> 256), COB=4
    deconv_k4s2_kernel<4, 8><<<dim3(8, 8, N * 1), dblk>>>(
        b1, dt2_w, dt2_b, outp, 64, 128, 128, 3, 2);

    // vq_loss -> last output element (deterministic fixed-order reduction)
    finalize_kernel<<<1, 256>>>(pbs, outp + (out_size - 1));
}

// round 16
// speedup vs baseline: 1.3520x; 1.3520x over previous
#include <cuda_runtime.h>
#include <math.h>

typedef unsigned long long ull;

// ---------------------------------------------------------------------------
// Scratch buffers (device globals; no allocation anywhere)
// b3r aliases g_buf1 during encoder (b1 dead after conv2 consumes it);
// bdr aliases g_buf3 during decoder (b3 dead after pvq).
// ---------------------------------------------------------------------------
__device__ float g_buf1[33554432];  // 32x64x128x128 (h1; enc relu view; deconv1 out)
__device__ float g_buf2[16777216];  // 32x128x64x64
__device__ float g_buf3[16777216];  // 32x128x64x64 (enc res state; dec relu view)
__device__ float g_buf4[4194304];   // 32x32x64x64  (res hidden, post-relu)
__device__ float g_z[8388608];      // 32x64x64x64
__device__ float g_q[8388608];      // 32x64x64x64
__device__ float g_d[16777216];     // 32x128x64x64 (dec res state)
__device__ float g_enorm[512];
__device__ float g_bsum[1024];

// ---------------------------------------------------------------------------
// Packed dual-fp32 helpers (FFMA2 via PTX fma.rn.f32x2; bit-identical to two
// scalar fmaf)
// ---------------------------------------------------------------------------
__device__ __forceinline__ ull pack2(float v) {
    ull p;
    asm("mov.b64 %0, {%1, %1};" : "=l"(p) : "f"(v));
    return p;
}
__device__ __forceinline__ void ffma2(ull& d, ull a, ull b) {
    asm("fma.rn.f32x2 %0, %1, %2, %0;" : "+l"(d) : "l"(a), "l"(b));
}
__device__ __forceinline__ float2 unpack2(ull p) {
    float2 r;
    asm("mov.b64 {%0, %1}, %2;" : "=f"(r.x), "=f"(r.y) : "l"(p));
    return r;
}
template<int NP>
__device__ __forceinline__ void load_w128(ull* wv, const float* p) {
    const ulonglong2* wq = reinterpret_cast<const ulonglong2*>(p);
    #pragma unroll
    for (int i = 0; i < NP / 2; i++) {
        ulonglong2 t = wq[i];
        wv[2 * i]     = t.x;
        wv[2 * i + 1] = t.y;
    }
}

// ---------------------------------------------------------------------------
// cp.async helpers
// ---------------------------------------------------------------------------
__device__ __forceinline__ void cp_async16(unsigned saddr, const void* g, bool valid) {
    int sz = valid ? 16 : 0;
    asm volatile("cp.async.cg.shared.global [%0], [%1], 16, %2;\n"
                 :: "r"(saddr), "l"(g), "r"(sz));
}
__device__ __forceinline__ void cp_async4(unsigned saddr, const void* g) {
    asm volatile("cp.async.ca.shared.global [%0], [%1], 4;\n"
                 :: "r"(saddr), "l"(g));
}
__device__ __forceinline__ void cp_commit() {
    asm volatile("cp.async.commit_group;\n" ::: "memory");
}
template<int N>
__device__ __forceinline__ void cp_wait() {
    asm volatile("cp.async.wait_group %0;\n" :: "n"(N) : "memory");
}

// ---------------------------------------------------------------------------
// 3x3 s1 p1 conv, 16B-cp.async double-buffered — the EXACT R12/R14 kernel
// that measured 220-244us (no in_relu path; input must be pre-relu'd).
// 16x16 out tile, 64 threads (8x8), 2x2 outputs x OCB oc per thread.
// Accumulation order: chunk -> ci -> kh -> kw (bit-identical to generic).
// Requires Cin % CB == 0, Win % 4 == 0.
// ---------------------------------------------------------------------------
template<int OCB, int CB>
__global__ void __launch_bounds__(64) conv3x3_async_kernel(
    const float* __restrict__ in, const float* __restrict__ w,
    const float* __restrict__ bias,
    float* __restrict__ out, float* __restrict__ out_relu,
    int Cin, int Hin, int Win, int Cout, int act)
{
    constexpr int TILE = 16;
    constexpr int ITY = 18, ITX = 24;
    constexpr int NP = OCB / 2;
    constexpr int IN_CHUNKS = CB * ITY * (ITX / 4);
    constexpr int W_ELE = CB * 9 * OCB;
    __shared__ __align__(16) float s_in[2][CB * ITY * ITX];
    __shared__ __align__(16) float s_w[2][W_ELE];

    const int Hout = Hin, Wout = Win;
    const int groups = Cout / OCB;
    const int n   = blockIdx.z / groups;
    const int oc0 = (blockIdx.z % groups) * OCB;
    const int ox0 = blockIdx.x * TILE;
    const int oy0 = blockIdx.y * TILE;
    const int tx = threadIdx.x, ty = threadIdx.y;   // 8x8
    const int tid = ty * 8 + tx;

    ull acc[2][2][NP];
    #pragma unroll
    for (int a = 0; a < 2; a++)
        #pragma unroll
        for (int b = 0; b < 2; b++)
            #pragma unroll
            for (int p = 0; p < NP; p++) acc[a][b][p] = 0ULL;

    const int iy0 = oy0 - 1;
    const int ix4 = ox0 - 4;          // 16B-aligned tile base
    const int nch = Cin / CB;

    auto load_stage = [&](int st, int c0) {
        unsigned sin = (unsigned)__cvta_generic_to_shared(&s_in[st][0]);
        for (int idx = tid; idx < IN_CHUNKS; idx += 64) {
            int ci  = idx / (ITY * 6);
            int r   = idx - ci * (ITY * 6);
            int row = r / 6, q = r - row * 6;
            int gy = iy0 + row;
            int gx = ix4 + q * 4;
            bool v = (gy >= 0 && gy < Hin && gx >= 0 && gx < Win);
            const float* gp = &in[((size_t)(n * Cin + c0 + ci) * Hin + (v ? gy : 0)) * Win
                                  + (v ? gx : 0)];
            cp_async16(sin + idx * 16, gp, v);
        }
        unsigned sw = (unsigned)__cvta_generic_to_shared(&s_w[st][0]);
        for (int idx = tid; idx < W_ELE; idx += 64) {
            int o  = idx % OCB;
            int r  = idx / OCB;
            int ci = r / 9;
            int kk = r - ci * 9;
            cp_async4(sw + idx * 4, &w[((size_t)(oc0 + o) * Cin + c0 + ci) * 9 + kk]);
        }
    };

    load_stage(0, 0);
    cp_commit();

    for (int ch = 0; ch < nch; ch++) {
        if (ch + 1 < nch) load_stage((ch + 1) & 1, (ch + 1) * CB);
        cp_commit();
        cp_wait<1>();
        __syncthreads();

        const int st = ch & 1;
        for (int ci = 0; ci < CB; ci++) {
            #pragma unroll
            for (int kh = 0; kh < 3; kh++) {
                // span cols tx*2+2 .. tx*2+7 (8B-aligned base); needed tmp[1..4]
                ull pk[2][4];
                #pragma unroll
                for (int dy = 0; dy < 2; dy++) {
                    const float2* rp = reinterpret_cast<const float2*>(
                        &s_in[st][(ci * ITY + ty * 2 + dy + kh) * ITX + tx * 2 + 2]);
                    float2 v0 = rp[0], v1 = rp[1], v2 = rp[2];
                    pk[dy][0] = pack2(v0.y);
                    pk[dy][1] = pack2(v1.x);
                    pk[dy][2] = pack2(v1.y);
                    pk[dy][3] = pack2(v2.x);
                }
                #pragma unroll
                for (int kw = 0; kw < 3; kw++) {
                    ull wv[NP];
                    load_w128<NP>(wv, &s_w[st][(ci * 9 + kh * 3 + kw) * OCB]);
                    #pragma unroll
                    for (int dy = 0; dy < 2; dy++) {
                        #pragma unroll
                        for (int dx = 0; dx < 2; dx++) {
                            #pragma unroll
                            for (int p = 0; p < NP; p++)
                                ffma2(acc[dy][dx][p], pk[dy][dx + kw], wv[p]);
                        }
                    }
                }
            }
        }
        __syncthreads();
    }

    #pragma unroll
    for (int dy = 0; dy < 2; dy++) {
        int oy = oy0 + ty * 2 + dy;
        if (oy >= Hout) continue;
        #pragma unroll
        for (int dx = 0; dx < 2; dx++) {
            int ox = ox0 + tx * 2 + dx;
            if (ox >= Wout) continue;
            #pragma unroll
            for (int p = 0; p < NP; p++) {
                float2 r2 = unpack2(acc[dy][dx][p]);
                #pragma unroll
                for (int h = 0; h < 2; h++) {
                    int o = 2 * p + h;
                    float v = (h ? r2.y : r2.x) + bias[oc0 + o];
                    int oidx = ((n * Cout + oc0 + o) * Hout + oy) * Wout + ox;
                    if (act == 1) v = fmaxf(v, 0.f);
                    out[oidx] = v;
                    if (out_relu) out_relu[oidx] = fmaxf(v, 0.f);
                }
            }
        }
    }
}

// ---------------------------------------------------------------------------
// Generic direct conv (R10 compute loop; R9-measured-neutral dual-write
// epilogue): 16x16 out tile, 64 threads, 2x2 outputs x OCB oc per thread.
// ---------------------------------------------------------------------------
template<int K, int S, int OCB, int CB>
__global__ void __launch_bounds__(64) conv2d_kernel(
    const float* __restrict__ in, const float* __restrict__ w,
    const float* __restrict__ bias, const float* __restrict__ resid,
    float* __restrict__ out, float* __restrict__ out_relu,
    int Cin, int Hin, int Win, int Cout, int Hout, int Wout,
    int pad, int in_relu, int act)
{
    constexpr int TILE = 16;
    constexpr int IT = TILE * S + K - S;
    constexpr int NP = OCB / 2;
    constexpr int SPAN = S + K;
    __shared__ __align__(16) float s_in[CB * IT * IT];
    __shared__ __align__(16) float s_w[CB * K * K * OCB];

    const int groups = Cout / OCB;
    const int n   = blockIdx.z / groups;
    const int oc0 = (blockIdx.z % groups) * OCB;
    const int ox0 = blockIdx.x * TILE;
    const int oy0 = blockIdx.y * TILE;
    const int tx = threadIdx.x, ty = threadIdx.y;
    const int tid = ty * 8 + tx;

    ull acc[2][2][NP];
    #pragma unroll
    for (int a = 0; a < 2; a++)
        #pragma unroll
        for (int b = 0; b < 2; b++)
            #pragma unroll
            for (int p = 0; p < NP; p++) acc[a][b][p] = 0ULL;

    const int ix0 = ox0 * S - pad;
    const int iy0 = oy0 * S - pad;

    for (int c0 = 0; c0 < Cin; c0 += CB) {
        const int cb = min(CB, Cin - c0);

        for (int idx = tid; idx < cb * IT * IT; idx += 64) {
            int ci = idx / (IT * IT);
            int r  = idx - ci * IT * IT;
            int iy = r / IT, ix = r - iy * IT;
            int gy = iy0 + iy, gx = ix0 + ix;
            float v = 0.f;
            if (gy >= 0 && gy < Hin && gx >= 0 && gx < Win)
                v = in[((n * Cin + c0 + ci) * Hin + gy) * Win + gx];
            if (in_relu) v = fmaxf(v, 0.f);
            s_in[idx] = v;
        }
        for (int idx = tid; idx < cb * K * K * OCB; idx += 64) {
            int o  = idx % OCB;
            int r  = idx / OCB;
            int ci = r / (K * K);
            int kk = r - ci * (K * K);
            s_w[idx] = w[((oc0 + o) * Cin + c0 + ci) * (K * K) + kk];
        }
        __syncthreads();

        for (int ci = 0; ci < cb; ci++) {
            #pragma unroll
            for (int kh = 0; kh < K; kh++) {
                ull pk[2][SPAN];
                #pragma unroll
                for (int dy = 0; dy < 2; dy++) {
                    const float2* rp = reinterpret_cast<const float2*>(
                        &s_in[(ci * IT + (ty * 2 + dy) * S + kh) * IT + tx * 2 * S]);
                    float tmp[SPAN];
                    #pragma unroll
                    for (int i = 0; i < SPAN / 2; i++) {
                        float2 v2 = rp[i];
                        tmp[2 * i]     = v2.x;
                        tmp[2 * i + 1] = v2.y;
                    }
                    #pragma unroll
                    for (int i = 0; i < SPAN; i++) pk[dy][i] = pack2(tmp[i]);
                }
                #pragma unroll
                for (int kw = 0; kw < K; kw++) {
                    ull wv[NP];
                    load_w128<NP>(wv, &s_w[((ci * K + kh) * K + kw) * OCB]);
                    #pragma unroll
                    for (int dy = 0; dy < 2; dy++) {
                        #pragma unroll
                        for (int dx = 0; dx < 2; dx++) {
                            #pragma unroll
                            for (int p = 0; p < NP; p++)
                                ffma2(acc[dy][dx][p], pk[dy][dx * S + kw], wv[p]);
                        }
                    }
                }
            }
        }
        __syncthreads();
    }

    #pragma unroll
    for (int dy = 0; dy < 2; dy++) {
        int oy = oy0 + ty * 2 + dy;
        if (oy >= Hout) continue;
        #pragma unroll
        for (int dx = 0; dx < 2; dx++) {
            int ox = ox0 + tx * 2 + dx;
            if (ox >= Wout) continue;
            #pragma unroll
            for (int p = 0; p < NP; p++) {
                float2 r2 = unpack2(acc[dy][dx][p]);
                #pragma unroll
                for (int h = 0; h < 2; h++) {
                    int o = 2 * p + h;
                    float v = (h ? r2.y : r2.x) + bias[oc0 + o];
                    int oidx = ((n * Cout + oc0 + o) * Hout + oy) * Wout + ox;
                    if (resid) v += resid[oidx];
                    if (act == 1)      v = fmaxf(v, 0.f);
                    else if (act == 2) v = tanhf(v);
                    out[oidx] = v;
                    if (out_relu) out_relu[oidx] = fmaxf(v, 0.f);
                }
            }
        }
    }
}

// ---------------------------------------------------------------------------
// ConvTranspose2d(k=4, s=2, p=1): R10 verbatim.
// ---------------------------------------------------------------------------
template<int COB, int CB>
__global__ void __launch_bounds__(128) deconv_k4s2_kernel(
    const float* __restrict__ in, const float* __restrict__ w,
    const float* __restrict__ bias, float* __restrict__ out,
    int Cin, int Hin, int Win, int Cout, int act)
{
    constexpr int NP = COB / 2;
    __shared__ __align__(16) float s_in[CB * 18 * 18];
    __shared__ __align__(16) float s_w[CB * 16 * COB];

    const int Hout = Hin * 2, Wout = Win * 2;
    const int groups = (Cout + COB - 1) / COB;
    const int n   = blockIdx.z / groups;
    const int co0 = (blockIdx.z % groups) * COB;
    const int uw0 = blockIdx.x * 16, uh0 = blockIdx.y * 16;
    const int tx = threadIdx.x, ty = threadIdx.y;   // 8x16
    const int tid = ty * 8 + tx;

    ull acc[2][2][2][NP];
    #pragma unroll
    for (int j = 0; j < 2; j++)
        #pragma unroll
        for (int py = 0; py < 2; py++)
            #pragma unroll
            for (int px = 0; px < 2; px++)
                #pragma unroll
                for (int p = 0; p < NP; p++) acc[j][py][px][p] = 0ULL;

    for (int c0 = 0; c0 < Cin; c0 += CB) {
        const int cb = min(CB, Cin - c0);
        for (int idx = tid; idx < cb * 324; idx += 128) {
            int ci = idx / 324;
            int r  = idx - ci * 324;
            int iy = r / 18, ix = r - iy * 18;
            int gy = uh0 - 1 + iy, gx = uw0 - 1 + ix;
            float v = 0.f;
            if (gy >= 0 && gy < Hin && gx >= 0 && gx < Win)
                v = in[((n * Cin + c0 + ci) * Hin + gy) * Win + gx];
            s_in[idx] = v;
        }
        for (int idx = tid; idx < cb * 16 * COB; idx += 128) {
            int o  = idx % COB;
            int r  = idx / COB;
            int ci = r / 16;
            int kk = r - ci * 16;
            float v = 0.f;
            if (co0 + o < Cout)
                v = w[((c0 + ci) * Cout + co0 + o) * 16 + kk];
            s_w[idx] = v;
        }
        __syncthreads();

        for (int ci = 0; ci < cb; ci++) {
            ull pk[3][4];
            #pragma unroll
            for (int r = 0; r < 3; r++) {
                const float2* rp = reinterpret_cast<const float2*>(
                    &s_in[(ci * 18 + ty + r) * 18 + tx * 2]);
                float2 a = rp[0], b = rp[1];
                pk[r][0] = pack2(a.x); pk[r][1] = pack2(a.y);
                pk[r][2] = pack2(b.x); pk[r][3] = pack2(b.y);
            }
            #pragma unroll
            for (int kh = 0; kh < 4; kh++) {
                const int py = (kh + 1) & 1;
                const int ro = (kh == 0) ? 2 : ((kh == 3) ? 0 : 1);
                #pragma unroll
                for (int kw = 0; kw < 4; kw++) {
                    const int px = (kw + 1) & 1;
                    const int co = (kw == 0) ? 2 : ((kw == 3) ? 0 : 1);
                    ull wv[NP];
                    load_w128<NP>(wv, &s_w[(ci * 16 + kh * 4 + kw) * COB]);
                    #pragma unroll
                    for (int j = 0; j < 2; j++) {
                        #pragma unroll
                        for (int p = 0; p < NP; p++)
                            ffma2(acc[j][py][px][p], pk[ro][j + co], wv[p]);
                    }
                }
            }
        }
        __syncthreads();
    }

    #pragma unroll
    for (int j = 0; j < 2; j++) {
        #pragma unroll
        for (int py = 0; py < 2; py++) {
            int oy = 2 * (uh0 + ty) + py;
            #pragma unroll
            for (int px = 0; px < 2; px++) {
                int ox = 2 * (uw0 + tx * 2 + j) + px;
                #pragma unroll
                for (int p = 0; p < NP; p++) {
                    float2 r2 = unpack2(acc[j][py][px][p]);
                    #pragma unroll
                    for (int h = 0; h < 2; h++) {
                        int o = 2 * p + h;
                        if (co0 + o < Cout) {
                            float v = (h ? r2.y : r2.x) + bias[co0 + o];
                            if (act == 1)      v = fmaxf(v, 0.f);
                            else if (act == 2) v = tanhf(v);
                            out[((n * Cout + co0 + o) * Hout + oy) * Wout + ox] = v;
                        }
                    }
                }
            }
        }
    }
}

// ---------------------------------------------------------------------------
// VQ kernels (R10 verbatim)
// ---------------------------------------------------------------------------
__global__ void vq_prep_kernel(const float* __restrict__ cb, float* __restrict__ enorm)
{
    int k = blockIdx.x * blockDim.x + threadIdx.x;
    if (k < 512) {
        float s = 0.f;
        #pragma unroll
        for (int d = 0; d < 64; d++) { float v = cb[k * 64 + d]; s += v * v; }
        enorm[k] = s;
    }
}

__global__ void __launch_bounds__(128) vq_kernel(
    const float* __restrict__ z, const float* __restrict__ cb,
    const float* __restrict__ enorm, float* __restrict__ q,
    float* __restrict__ bsum)
{
    __shared__ __align__(16) float sc[64 * 66];
    __shared__ float se[64];
    __shared__ float sred[128];

    const int tid = threadIdx.x;
    const int v   = blockIdx.x * 128 + tid;
    const int b   = v >> 12;
    const int hw  = v & 4095;

    const float* zp = z + b * 64 * 4096 + hw;
    float zr[64];
    float znorm = 0.f;
    #pragma unroll
    for (int d = 0; d < 64; d++) { zr[d] = zp[d * 4096]; znorm += zr[d] * zr[d]; }

    float best = 3.402823e38f;
    int   bi   = 0;
    for (int c0 = 0; c0 < 512; c0 += 64) {
        __syncthreads();
        for (int i = tid; i < 4096; i += 128) {
            int c = i >> 6, d = i & 63;
            sc[d * 66 + c] = cb[(c0 + c) * 64 + d];
        }
        if (tid < 64) se[tid] = enorm[c0 + tid];
        __syncthreads();
        #pragma unroll
        for (int g = 0; g < 4; g++) {
            ull dp[8];
            #pragma unroll
            for (int p = 0; p < 8; p++) dp[p] = 0ULL;
            #pragma unroll
            for (int d = 0; d < 64; d++) {
                ull z2 = pack2(zr[d]);
                const ull* row = (const ull*)&sc[d * 66 + g * 16];
                #pragma unroll
                for (int p = 0; p < 8; p++) ffma2(dp[p], z2, row[p]);
            }
            #pragma unroll
            for (int p = 0; p < 8; p++) {
                float2 dd = unpack2(dp[p]);
                int c = g * 16 + 2 * p;
                float dist0 = znorm - 2.f * dd.x + se[c];
                if (dist0 < best) { best = dist0; bi = c0 + c; }
                float dist1 = znorm - 2.f * dd.y + se[c + 1];
                if (dist1 < best) { best = dist1; bi = c0 + c + 1; }
            }
        }
    }

    const float* e = cb + bi * 64;
    float* qp = q + b * 64 * 4096 + hw;
    float err = 0.f;
    #pragma unroll
    for (int d = 0; d < 64; d++) {
        float ev = e[d];
        float df = ev - zr[d];
        err += df * df;
        qp[d * 4096] = ev;
    }

    sred[tid] = err;
    __syncthreads();
    for (int s = 64; s > 0; s >>= 1) {
        if (tid < s) sred[tid] += sred[tid + s];
        __syncthreads();
    }
    if (tid == 0) bsum[blockIdx.x] = sred[0];
}

__global__ void finalize_kernel(const float* __restrict__ bsum, float* __restrict__ out_loss)
{
    __shared__ float s[256];
    int t = threadIdx.x;
    float v = 0.f;
    for (int i = t; i < 1024; i += 256) v += bsum[i];
    s[t] = v;
    __syncthreads();
    for (int k = 128; k > 0; k >>= 1) {
        if (t < k) s[t] += s[t + k];
        __syncthreads();
    }
    if (t == 0) out_loss[0] = 1.25f * s[0] / 8388608.0f;
}

// ---------------------------------------------------------------------------
// Launcher: R10 geometry; res 3x3 -> measured-fast async kernel fed by
// relu views produced via dual-write epilogues on conv3/dec1/1x1.
// ---------------------------------------------------------------------------
extern "C" void kernel_launch(void* const* d_in, const int* in_sizes, int n_in,
                              void* d_out, int out_size)
{
    const float* x        = (const float*)d_in[0];
    const float* enc_w1   = (const float*)d_in[1];
    const float* enc_b1   = (const float*)d_in[2];
    const float* enc_w2   = (const float*)d_in[3];
    const float* enc_b2   = (const float*)d_in[4];
    const float* enc_w3   = (const float*)d_in[5];
    const float* enc_b3   = (const float*)d_in[6];
    const float* enc_rw1  = (const float*)d_in[7];
    const float* enc_rb1  = (const float*)d_in[8];
    const float* enc_rw2  = (const float*)d_in[9];
    const float* enc_rb2  = (const float*)d_in[10];
    const float* pvq_w    = (const float*)d_in[11];
    const float* pvq_b    = (const float*)d_in[12];
    const float* codebook = (const float*)d_in[13];
    const float* dec_w1   = (const float*)d_in[14];
    const float* dec_b1   = (const float*)d_in[15];
    const float* dec_rw1  = (const float*)d_in[16];
    const float* dec_rb1  = (const float*)d_in[17];
    const float* dec_rw2  = (const float*)d_in[18];
    const float* dec_rb2  = (const float*)d_in[19];
    const float* dt1_w    = (const float*)d_in[20];
    const float* dt1_b    = (const float*)d_in[21];
    const float* dt2_w    = (const float*)d_in[22];
    const float* dt2_b    = (const float*)d_in[23];
    float* outp = (float*)d_out;

    static float *b1 = nullptr, *b2, *b3, *b4, *bz, *bq, *bd, *pe, *pbs;
    if (!b1) {
        cudaGetSymbolAddress((void**)&b1,  g_buf1);
        cudaGetSymbolAddress((void**)&b2,  g_buf2);
        cudaGetSymbolAddress((void**)&b3,  g_buf3);
        cudaGetSymbolAddress((void**)&b4,  g_buf4);
        cudaGetSymbolAddress((void**)&bz,  g_z);
        cudaGetSymbolAddress((void**)&bq,  g_q);
        cudaGetSymbolAddress((void**)&bd,  g_d);
        cudaGetSymbolAddress((void**)&pe,  g_enorm);
        cudaGetSymbolAddress((void**)&pbs, g_bsum);
    }
    float* b3r = b1;   // relu view of enc res state (b1 dead after conv2)
    float* bdr = b3;   // relu view of dec res state (b3 dead after pvq)

    const dim3 blk(8, 8);      // 64 threads, 16x16 output tile
    const dim3 dblk(8, 16);
    const int N = 32;

    // ---- Encoder ----
    // conv1: 3->64, k4 s2 p1, relu  (256 -> 128)
    conv2d_kernel<4, 2, 16, 4><<<dim3(8, 8, N * (64 / 16)), blk>>>(
        x, enc_w1, enc_b1, nullptr, b1, nullptr, 3, 256, 256, 64, 128, 128, 1, 0, 1);
    // conv2: 64->128, k4 s2 p1, relu  (128 -> 64)
    conv2d_kernel<4, 2, 16, 4><<<dim3(4, 4, N * (128 / 16)), blk>>>(
        b1, enc_w2, enc_b2, nullptr, b2, nullptr, 64, 128, 128, 128, 64, 64, 1, 0, 1);
    // conv3: 128->128, k3 s1 p1 (generic, dual-write pre-act b3 + relu b3r)
    conv2d_kernel<3, 1, 16, 8><<<dim3(4, 4, N * (128 / 16)), blk>>>(
        b2, enc_w3, enc_b3, nullptr, b3, b3r, 128, 64, 64, 128, 64, 64, 1, 0, 0);
    // residual stack x2: async 3x3 reads relu view, writes relu(h);
    // 1x1 updates b3 and refreshes relu view.
    for (int i = 0; i < 2; i++) {
        const float* w1p = enc_rw1 + (size_t)i * 32 * 128 * 9;
        const float* b1p = enc_rb1 + i * 32;
        const float* w2p = enc_rw2 + (size_t)i * 128 * 32;
        const float* b2p = enc_rb2 + i * 128;
        conv3x3_async_kernel<8, 8><<<dim3(4, 4, N * (32 / 8)), blk>>>(
            b3r, w1p, b1p, b4, nullptr, 128, 64, 64, 32, 1);
        conv2d_kernel<1, 1, 16, 16><<<dim3(4, 4, N * (128 / 16)), blk>>>(
            b4, w2p, b2p, b3, b3, b3r, 32, 64, 64, 128, 64, 64, 0, 0, 0);
    }
    // pre-VQ 1x1: 128->64 (reads relu view == relu(x_final))
    conv2d_kernel<1, 1, 16, 16><<<dim3(4, 4, N * (64 / 16)), blk>>>(
        b3r, pvq_w, pvq_b, nullptr, bz, nullptr, 128, 64, 64, 64, 64, 64, 0, 0, 0);

    // ---- VQ ----
    vq_prep_kernel<<<2, 256>>>(codebook, pe);
    vq_kernel<<<1024, 128>>>(bz, codebook, pe, bq, pbs);

    // ---- Decoder ----
    // dec conv1: 64->128, k3 s1 p1 (generic, dual-write bd + relu bdr)
    conv2d_kernel<3, 1, 16, 8><<<dim3(4, 4, N * (128 / 16)), blk>>>(
        bq, dec_w1, dec_b1, nullptr, bd, bdr, 64, 64, 64, 128, 64, 64, 1, 0, 0);
    // residual stack x2
    for (int i = 0; i < 2; i++) {
        const float* w1p = dec_rw1 + (size_t)i * 32 * 128 * 9;
        const float* b1p = dec_rb1 + i * 32;
        const float* w2p = dec_rw2 + (size_t)i * 128 * 32;
        const float* b2p = dec_rb2 + i * 128;
        conv3x3_async_kernel<8, 8><<<dim3(4, 4, N * (32 / 8)), blk>>>(
            bdr, w1p, b1p, b4, nullptr, 128, 64, 64, 32, 1);
        conv2d_kernel<1, 1, 16, 16><<<dim3(4, 4, N * (128 / 16)), blk>>>(
            b4, w2p, b2p, bd, bd, bdr, 32, 64, 64, 128, 64, 64, 0, 0, 0);
    }
    // deconv1: 128->64, relu  (64 -> 128); reads relu view
    deconv_k4s2_kernel<8, 8><<<dim3(4, 4, N * (64 / 8)), dblk>>>(
        bdr, dt1_w, dt1_b, b1, 128, 64, 64, 64, 1);
    // deconv2: 64->3, tanh  (128 -> 256), COB=4
    deconv_k4s2_kernel<4, 8><<<dim3(8, 8, N * 1), dblk>>>(
        b1, dt2_w, dt2_b, outp, 64, 128, 128, 3, 2);

    // vq_loss -> last output element (deterministic fixed-order reduction)
    finalize_kernel<<<1, 256>>>(pbs, outp + (out_size - 1));
}

// round 17
// speedup vs baseline: 1.7584x; 1.3006x over previous
#include <cuda_runtime.h>
#include <math.h>

typedef unsigned long long ull;

// ---------------------------------------------------------------------------
// Scratch buffers (device globals; no allocation anywhere)
// ---------------------------------------------------------------------------
__device__ float g_buf1[33554432];  // 32x64x128x128 (h1, later deconv1 out)
__device__ float g_buf2[16777216];  // 32x128x64x64
__device__ float g_buf3[16777216];  // 32x128x64x64 (enc res state)
__device__ float g_buf4[4194304];   // 32x32x64x64  (res hidden)
__device__ float g_z[8388608];      // 32x64x64x64
__device__ float g_q[8388608];      // 32x64x64x64
__device__ float g_d[16777216];     // 32x128x64x64 (dec res state)
__device__ float g_enorm[512];
__device__ float g_bsum[1024];

// ---------------------------------------------------------------------------
// Packed dual-fp32 helpers (FFMA2 via PTX fma.rn.f32x2; bit-identical to two
// scalar fmaf)
// ---------------------------------------------------------------------------
__device__ __forceinline__ ull pack2(float v) {
    ull p;
    asm("mov.b64 %0, {%1, %1};" : "=l"(p) : "f"(v));
    return p;
}
__device__ __forceinline__ void ffma2(ull& d, ull a, ull b) {
    asm("fma.rn.f32x2 %0, %1, %2, %0;" : "+l"(d) : "l"(a), "l"(b));
}
__device__ __forceinline__ float2 unpack2(ull p) {
    float2 r;
    asm("mov.b64 {%0, %1}, %2;" : "=f"(r.x), "=f"(r.y) : "l"(p));
    return r;
}
template<int NP>
__device__ __forceinline__ void load_w128(ull* wv, const float* p) {
    const ulonglong2* wq = reinterpret_cast<const ulonglong2*>(p);
    #pragma unroll
    for (int i = 0; i < NP / 2; i++) {
        ulonglong2 t = wq[i];
        wv[2 * i]     = t.x;
        wv[2 * i + 1] = t.y;
    }
}

// ---------------------------------------------------------------------------
// cp.async helpers
// ---------------------------------------------------------------------------
__device__ __forceinline__ void cp_async16(unsigned saddr, const void* g, bool valid) {
    int sz = valid ? 16 : 0;
    asm volatile("cp.async.cg.shared.global [%0], [%1], 16, %2;\n"
                 :: "r"(saddr), "l"(g), "r"(sz));
}
__device__ __forceinline__ void cp_async4(unsigned saddr, const void* g) {
    asm volatile("cp.async.ca.shared.global [%0], [%1], 4;\n"
                 :: "r"(saddr), "l"(g));
}
__device__ __forceinline__ void cp_commit() {
    asm volatile("cp.async.commit_group;\n" ::: "memory");
}
template<int N>
__device__ __forceinline__ void cp_wait() {
    asm volatile("cp.async.wait_group %0;\n" :: "n"(N) : "memory");
}

// ---------------------------------------------------------------------------
// Generic direct conv (R10 verbatim): 16x16 out tile, 64 threads,
// 2x2 outputs x OCB oc per thread (packed pairs).
// ---------------------------------------------------------------------------
template<int K, int S, int OCB, int CB>
__global__ void __launch_bounds__(64) conv2d_kernel(
    const float* __restrict__ in, const float* __restrict__ w,
    const float* __restrict__ bias, const float* __restrict__ resid,
    float* __restrict__ out,
    int Cin, int Hin, int Win, int Cout, int Hout, int Wout,
    int pad, int in_relu, int act)
{
    constexpr int TILE = 16;
    constexpr int IT = TILE * S + K - S;
    constexpr int NP = OCB / 2;
    constexpr int SPAN = S + K;
    __shared__ __align__(16) float s_in[CB * IT * IT];
    __shared__ __align__(16) float s_w[CB * K * K * OCB];

    const int groups = Cout / OCB;
    const int n   = blockIdx.z / groups;
    const int oc0 = (blockIdx.z % groups) * OCB;
    const int ox0 = blockIdx.x * TILE;
    const int oy0 = blockIdx.y * TILE;
    const int tx = threadIdx.x, ty = threadIdx.y;
    const int tid = ty * 8 + tx;

    ull acc[2][2][NP];
    #pragma unroll
    for (int a = 0; a < 2; a++)
        #pragma unroll
        for (int b = 0; b < 2; b++)
            #pragma unroll
            for (int p = 0; p < NP; p++) acc[a][b][p] = 0ULL;

    const int ix0 = ox0 * S - pad;
    const int iy0 = oy0 * S - pad;

    for (int c0 = 0; c0 < Cin; c0 += CB) {
        const int cb = min(CB, Cin - c0);

        for (int idx = tid; idx < cb * IT * IT; idx += 64) {
            int ci = idx / (IT * IT);
            int r  = idx - ci * IT * IT;
            int iy = r / IT, ix = r - iy * IT;
            int gy = iy0 + iy, gx = ix0 + ix;
            float v = 0.f;
            if (gy >= 0 && gy < Hin && gx >= 0 && gx < Win)
                v = in[((n * Cin + c0 + ci) * Hin + gy) * Win + gx];
            if (in_relu) v = fmaxf(v, 0.f);
            s_in[idx] = v;
        }
        for (int idx = tid; idx < cb * K * K * OCB; idx += 64) {
            int o  = idx % OCB;
            int r  = idx / OCB;
            int ci = r / (K * K);
            int kk = r - ci * (K * K);
            s_w[idx] = w[((oc0 + o) * Cin + c0 + ci) * (K * K) + kk];
        }
        __syncthreads();

        for (int ci = 0; ci < cb; ci++) {
            #pragma unroll
            for (int kh = 0; kh < K; kh++) {
                ull pk[2][SPAN];
                #pragma unroll
                for (int dy = 0; dy < 2; dy++) {
                    const float2* rp = reinterpret_cast<const float2*>(
                        &s_in[(ci * IT + (ty * 2 + dy) * S + kh) * IT + tx * 2 * S]);
                    float tmp[SPAN];
                    #pragma unroll
                    for (int i = 0; i < SPAN / 2; i++) {
                        float2 v2 = rp[i];
                        tmp[2 * i]     = v2.x;
                        tmp[2 * i + 1] = v2.y;
                    }
                    #pragma unroll
                    for (int i = 0; i < SPAN; i++) pk[dy][i] = pack2(tmp[i]);
                }
                #pragma unroll
                for (int kw = 0; kw < K; kw++) {
                    ull wv[NP];
                    load_w128<NP>(wv, &s_w[((ci * K + kh) * K + kw) * OCB]);
                    #pragma unroll
                    for (int dy = 0; dy < 2; dy++) {
                        #pragma unroll
                        for (int dx = 0; dx < 2; dx++) {
                            #pragma unroll
                            for (int p = 0; p < NP; p++)
                                ffma2(acc[dy][dx][p], pk[dy][dx * S + kw], wv[p]);
                        }
                    }
                }
            }
        }
        __syncthreads();
    }

    #pragma unroll
    for (int dy = 0; dy < 2; dy++) {
        int oy = oy0 + ty * 2 + dy;
        if (oy >= Hout) continue;
        #pragma unroll
        for (int dx = 0; dx < 2; dx++) {
            int ox = ox0 + tx * 2 + dx;
            if (ox >= Wout) continue;
            #pragma unroll
            for (int p = 0; p < NP; p++) {
                float2 r2 = unpack2(acc[dy][dx][p]);
                #pragma unroll
                for (int h = 0; h < 2; h++) {
                    int o = 2 * p + h;
                    float v = (h ? r2.y : r2.x) + bias[oc0 + o];
                    int oidx = ((n * Cout + oc0 + o) * Hout + oy) * Wout + ox;
                    if (resid) v += resid[oidx];
                    if (act == 1)      v = fmaxf(v, 0.f);
                    else if (act == 2) v = tanhf(v);
                    out[oidx] = v;
                }
            }
        }
    }
}

// ---------------------------------------------------------------------------
// ConvTranspose2d(k=4, s=2, p=1): R10 verbatim (used for deconv2).
// ---------------------------------------------------------------------------
template<int COB, int CB>
__global__ void __launch_bounds__(128) deconv_k4s2_kernel(
    const float* __restrict__ in, const float* __restrict__ w,
    const float* __restrict__ bias, float* __restrict__ out,
    int Cin, int Hin, int Win, int Cout, int act)
{
    constexpr int NP = COB / 2;
    __shared__ __align__(16) float s_in[CB * 18 * 18];
    __shared__ __align__(16) float s_w[CB * 16 * COB];

    const int Hout = Hin * 2, Wout = Win * 2;
    const int groups = (Cout + COB - 1) / COB;
    const int n   = blockIdx.z / groups;
    const int co0 = (blockIdx.z % groups) * COB;
    const int uw0 = blockIdx.x * 16, uh0 = blockIdx.y * 16;
    const int tx = threadIdx.x, ty = threadIdx.y;   // 8x16
    const int tid = ty * 8 + tx;

    ull acc[2][2][2][NP];
    #pragma unroll
    for (int j = 0; j < 2; j++)
        #pragma unroll
        for (int py = 0; py < 2; py++)
            #pragma unroll
            for (int px = 0; px < 2; px++)
                #pragma unroll
                for (int p = 0; p < NP; p++) acc[j][py][px][p] = 0ULL;

    for (int c0 = 0; c0 < Cin; c0 += CB) {
        const int cb = min(CB, Cin - c0);
        for (int idx = tid; idx < cb * 324; idx += 128) {
            int ci = idx / 324;
            int r  = idx - ci * 324;
            int iy = r / 18, ix = r - iy * 18;
            int gy = uh0 - 1 + iy, gx = uw0 - 1 + ix;
            float v = 0.f;
            if (gy >= 0 && gy < Hin && gx >= 0 && gx < Win)
                v = in[((n * Cin + c0 + ci) * Hin + gy) * Win + gx];
            s_in[idx] = v;
        }
        for (int idx = tid; idx < cb * 16 * COB; idx += 128) {
            int o  = idx % COB;
            int r  = idx / COB;
            int ci = r / 16;
            int kk = r - ci * 16;
            float v = 0.f;
            if (co0 + o < Cout)
                v = w[((c0 + ci) * Cout + co0 + o) * 16 + kk];
            s_w[idx] = v;
        }
        __syncthreads();

        for (int ci = 0; ci < cb; ci++) {
            ull pk[3][4];
            #pragma unroll
            for (int r = 0; r < 3; r++) {
                const float2* rp = reinterpret_cast<const float2*>(
                    &s_in[(ci * 18 + ty + r) * 18 + tx * 2]);
                float2 a = rp[0], b = rp[1];
                pk[r][0] = pack2(a.x); pk[r][1] = pack2(a.y);
                pk[r][2] = pack2(b.x); pk[r][3] = pack2(b.y);
            }
            #pragma unroll
            for (int kh = 0; kh < 4; kh++) {
                const int py = (kh + 1) & 1;
                const int ro = (kh == 0) ? 2 : ((kh == 3) ? 0 : 1);
                #pragma unroll
                for (int kw = 0; kw < 4; kw++) {
                    const int px = (kw + 1) & 1;
                    const int co = (kw == 0) ? 2 : ((kw == 3) ? 0 : 1);
                    ull wv[NP];
                    load_w128<NP>(wv, &s_w[(ci * 16 + kh * 4 + kw) * COB]);
                    #pragma unroll
                    for (int j = 0; j < 2; j++) {
                        #pragma unroll
                        for (int p = 0; p < NP; p++)
                            ffma2(acc[j][py][px][p], pk[ro][j + co], wv[p]);
                    }
                }
            }
        }
        __syncthreads();
    }

    #pragma unroll
    for (int j = 0; j < 2; j++) {
        #pragma unroll
        for (int py = 0; py < 2; py++) {
            int oy = 2 * (uh0 + ty) + py;
            #pragma unroll
            for (int px = 0; px < 2; px++) {
                int ox = 2 * (uw0 + tx * 2 + j) + px;
                #pragma unroll
                for (int p = 0; p < NP; p++) {
                    float2 r2 = unpack2(acc[j][py][px][p]);
                    #pragma unroll
                    for (int h = 0; h < 2; h++) {
                        int o = 2 * p + h;
                        if (co0 + o < Cout) {
                            float v = (h ? r2.y : r2.x) + bias[co0 + o];
                            if (act == 1)      v = fmaxf(v, 0.f);
                            else if (act == 2) v = tanhf(v);
                            out[((n * Cout + co0 + o) * Hout + oy) * Wout + ox] = v;
                        }
                    }
                }
            }
        }
    }
}

// ---------------------------------------------------------------------------
// ConvTranspose2d(k=4, s=2, p=1) with 16B-cp.async double-buffered loads.
// Same compute loop / accumulation order as the generic deconv (bit-identical).
// Input tile 18 rows x 24 cols, col base uw0-4 so every 16B chunk is fully
// valid or fully OOB (zfill). Requires Cin % CB == 0, Cout % COB == 0,
// Win % 4 == 0. No input transform (input must already be post-activation).
// ---------------------------------------------------------------------------
template<int COB, int CB>
__global__ void __launch_bounds__(128) deconv_k4s2_async_kernel(
    const float* __restrict__ in, const float* __restrict__ w,
    const float* __restrict__ bias, float* __restrict__ out,
    int Cin, int Hin, int Win, int Cout, int act)
{
    constexpr int NP = COB / 2;
    constexpr int ITY = 18, ITX = 24;
    constexpr int IN_CHUNKS = CB * ITY * (ITX / 4);
    constexpr int W_ELE = CB * 16 * COB;
    __shared__ __align__(16) float s_in[2][CB * ITY * ITX];
    __shared__ __align__(16) float s_w[2][W_ELE];

    const int Hout = Hin * 2, Wout = Win * 2;
    const int groups = Cout / COB;
    const int n   = blockIdx.z / groups;
    const int co0 = (blockIdx.z % groups) * COB;
    const int uw0 = blockIdx.x * 16, uh0 = blockIdx.y * 16;
    const int tx = threadIdx.x, ty = threadIdx.y;   // 8x16
    const int tid = ty * 8 + tx;

    ull acc[2][2][2][NP];   // [j(uw)][py][px][pair]
    #pragma unroll
    for (int j = 0; j < 2; j++)
        #pragma unroll
        for (int py = 0; py < 2; py++)
            #pragma unroll
            for (int px = 0; px < 2; px++)
                #pragma unroll
                for (int p = 0; p < NP; p++) acc[j][py][px][p] = 0ULL;

    const int iy0 = uh0 - 1;
    const int ix4 = uw0 - 4;          // 16B-aligned tile base
    const int nch = Cin / CB;

    auto load_stage = [&](int st, int c0) {
        unsigned sin = (unsigned)__cvta_generic_to_shared(&s_in[st][0]);
        for (int idx = tid; idx < IN_CHUNKS; idx += 128) {
            int ci  = idx / (ITY * 6);
            int r   = idx - ci * (ITY * 6);
            int row = r / 6, q = r - row * 6;
            int gy = iy0 + row;
            int gx = ix4 + q * 4;
            bool v = (gy >= 0 && gy < Hin && gx >= 0 && gx < Win);
            const float* gp = &in[((size_t)(n * Cin + c0 + ci) * Hin + (v ? gy : 0)) * Win
                                  + (v ? gx : 0)];
            cp_async16(sin + idx * 16, gp, v);
        }
        unsigned sw = (unsigned)__cvta_generic_to_shared(&s_w[st][0]);
        for (int idx = tid; idx < W_ELE; idx += 128) {
            int o  = idx % COB;
            int r  = idx / COB;
            int ci = r / 16;
            int kk = r - ci * 16;
            cp_async4(sw + idx * 4,
                      &w[((size_t)(c0 + ci) * Cout + co0 + o) * 16 + kk]);
        }
    };

    load_stage(0, 0);
    cp_commit();

    for (int ch = 0; ch < nch; ch++) {
        if (ch + 1 < nch) load_stage((ch + 1) & 1, (ch + 1) * CB);
        cp_commit();
        cp_wait<1>();
        __syncthreads();

        const int st = ch & 1;
        for (int ci = 0; ci < CB; ci++) {
            // rows ty+0..2 (from uh0-1); aligned span cols tx*2+2..tx*2+7,
            // needed global cols uw0-1+tx*2 .. uw0+2+tx*2 -> {v0.y,v1.x,v1.y,v2.x}
            ull pk[3][4];
            #pragma unroll
            for (int r = 0; r < 3; r++) {
                const float2* rp = reinterpret_cast<const float2*>(
                    &s_in[st][(ci * ITY + ty + r) * ITX + tx * 2 + 2]);
                float2 v0 = rp[0], v1 = rp[1], v2 = rp[2];
                pk[r][0] = pack2(v0.y);
                pk[r][1] = pack2(v1.x);
                pk[r][2] = pack2(v1.y);
                pk[r][3] = pack2(v2.x);
            }
            #pragma unroll
            for (int kh = 0; kh < 4; kh++) {
                const int py = (kh + 1) & 1;
                const int ro = (kh == 0) ? 2 : ((kh == 3) ? 0 : 1);
                #pragma unroll
                for (int kw = 0; kw < 4; kw++) {
                    const int px = (kw + 1) & 1;
                    const int co = (kw == 0) ? 2 : ((kw == 3) ? 0 : 1);
                    ull wv[NP];
                    load_w128<NP>(wv, &s_w[st][(ci * 16 + kh * 4 + kw) * COB]);
                    #pragma unroll
                    for (int j = 0; j < 2; j++) {
                        #pragma unroll
                        for (int p = 0; p < NP; p++)
                            ffma2(acc[j][py][px][p], pk[ro][j + co], wv[p]);
                    }
                }
            }
        }
        __syncthreads();
    }

    #pragma unroll
    for (int j = 0; j < 2; j++) {
        #pragma unroll
        for (int py = 0; py < 2; py++) {
            int oy = 2 * (uh0 + ty) + py;
            #pragma unroll
            for (int px = 0; px < 2; px++) {
                int ox = 2 * (uw0 + tx * 2 + j) + px;
                #pragma unroll
                for (int p = 0; p < NP; p++) {
                    float2 r2 = unpack2(acc[j][py][px][p]);
                    #pragma unroll
                    for (int h = 0; h < 2; h++) {
                        int o = 2 * p + h;
                        float v = (h ? r2.y : r2.x) + bias[co0 + o];
                        if (act == 1)      v = fmaxf(v, 0.f);
                        else if (act == 2) v = tanhf(v);
                        out[((n * Cout + co0 + o) * Hout + oy) * Wout + ox] = v;
                    }
                }
            }
        }
    }
}

// ---------------------------------------------------------------------------
// VQ kernels (R10 verbatim)
// ---------------------------------------------------------------------------
__global__ void vq_prep_kernel(const float* __restrict__ cb, float* __restrict__ enorm)
{
    int k = blockIdx.x * blockDim.x + threadIdx.x;
    if (k < 512) {
        float s = 0.f;
        #pragma unroll
        for (int d = 0; d < 64; d++) { float v = cb[k * 64 + d]; s += v * v; }
        enorm[k] = s;
    }
}

__global__ void __launch_bounds__(128) vq_kernel(
    const float* __restrict__ z, const float* __restrict__ cb,
    const float* __restrict__ enorm, float* __restrict__ q,
    float* __restrict__ bsum)
{
    __shared__ __align__(16) float sc[64 * 66];
    __shared__ float se[64];
    __shared__ float sred[128];

    const int tid = threadIdx.x;
    const int v   = blockIdx.x * 128 + tid;
    const int b   = v >> 12;
    const int hw  = v & 4095;

    const float* zp = z + b * 64 * 4096 + hw;
    float zr[64];
    float znorm = 0.f;
    #pragma unroll
    for (int d = 0; d < 64; d++) { zr[d] = zp[d * 4096]; znorm += zr[d] * zr[d]; }

    float best = 3.402823e38f;
    int   bi   = 0;
    for (int c0 = 0; c0 < 512; c0 += 64) {
        __syncthreads();
        for (int i = tid; i < 4096; i += 128) {
            int c = i >> 6, d = i & 63;
            sc[d * 66 + c] = cb[(c0 + c) * 64 + d];
        }
        if (tid < 64) se[tid] = enorm[c0 + tid];
        __syncthreads();
        #pragma unroll
        for (int g = 0; g < 4; g++) {
            ull dp[8];
            #pragma unroll
            for (int p = 0; p < 8; p++) dp[p] = 0ULL;
            #pragma unroll
            for (int d = 0; d < 64; d++) {
                ull z2 = pack2(zr[d]);
                const ull* row = (const ull*)&sc[d * 66 + g * 16];
                #pragma unroll
                for (int p = 0; p < 8; p++) ffma2(dp[p], z2, row[p]);
            }
            #pragma unroll
            for (int p = 0; p < 8; p++) {
                float2 dd = unpack2(dp[p]);
                int c = g * 16 + 2 * p;
                float dist0 = znorm - 2.f * dd.x + se[c];
                if (dist0 < best) { best = dist0; bi = c0 + c; }
                float dist1 = znorm - 2.f * dd.y + se[c + 1];
                if (dist1 < best) { best = dist1; bi = c0 + c + 1; }
            }
        }
    }

    const float* e = cb + bi * 64;
    float* qp = q + b * 64 * 4096 + hw;
    float err = 0.f;
    #pragma unroll
    for (int d = 0; d < 64; d++) {
        float ev = e[d];
        float df = ev - zr[d];
        err += df * df;
        qp[d * 4096] = ev;
    }

    sred[tid] = err;
    __syncthreads();
    for (int s = 64; s > 0; s >>= 1) {
        if (tid < s) sred[tid] += sred[tid + s];
        __syncthreads();
    }
    if (tid == 0) bsum[blockIdx.x] = sred[0];
}

__global__ void finalize_kernel(const float* __restrict__ bsum, float* __restrict__ out_loss)
{
    __shared__ float s[256];
    int t = threadIdx.x;
    float v = 0.f;
    for (int i = t; i < 1024; i += 256) v += bsum[i];
    s[t] = v;
    __syncthreads();
    for (int k = 128; k > 0; k >>= 1) {
        if (t < k) s[t] += s[t + k];
        __syncthreads();
    }
    if (t == 0) out_loss[0] = 1.25f * s[0] / 8388608.0f;
}

// ---------------------------------------------------------------------------
// Launcher: R10 verbatim except deconv1 -> async variant.
// ---------------------------------------------------------------------------
extern "C" void kernel_launch(void* const* d_in, const int* in_sizes, int n_in,
                              void* d_out, int out_size)
{
    const float* x        = (const float*)d_in[0];
    const float* enc_w1   = (const float*)d_in[1];
    const float* enc_b1   = (const float*)d_in[2];
    const float* enc_w2   = (const float*)d_in[3];
    const float* enc_b2   = (const float*)d_in[4];
    const float* enc_w3   = (const float*)d_in[5];
    const float* enc_b3   = (const float*)d_in[6];
    const float* enc_rw1  = (const float*)d_in[7];
    const float* enc_rb1  = (const float*)d_in[8];
    const float* enc_rw2  = (const float*)d_in[9];
    const float* enc_rb2  = (const float*)d_in[10];
    const float* pvq_w    = (const float*)d_in[11];
    const float* pvq_b    = (const float*)d_in[12];
    const float* codebook = (const float*)d_in[13];
    const float* dec_w1   = (const float*)d_in[14];
    const float* dec_b1   = (const float*)d_in[15];
    const float* dec_rw1  = (const float*)d_in[16];
    const float* dec_rb1  = (const float*)d_in[17];
    const float* dec_rw2  = (const float*)d_in[18];
    const float* dec_rb2  = (const float*)d_in[19];
    const float* dt1_w    = (const float*)d_in[20];
    const float* dt1_b    = (const float*)d_in[21];
    const float* dt2_w    = (const float*)d_in[22];
    const float* dt2_b    = (const float*)d_in[23];
    float* outp = (float*)d_out;

    static float *b1 = nullptr, *b2, *b3, *b4, *bz, *bq, *bd, *pe, *pbs;
    if (!b1) {
        cudaGetSymbolAddress((void**)&b1,  g_buf1);
        cudaGetSymbolAddress((void**)&b2,  g_buf2);
        cudaGetSymbolAddress((void**)&b3,  g_buf3);
        cudaGetSymbolAddress((void**)&b4,  g_buf4);
        cudaGetSymbolAddress((void**)&bz,  g_z);
        cudaGetSymbolAddress((void**)&bq,  g_q);
        cudaGetSymbolAddress((void**)&bd,  g_d);
        cudaGetSymbolAddress((void**)&pe,  g_enorm);
        cudaGetSymbolAddress((void**)&pbs, g_bsum);
    }

    const dim3 blk(8, 8);      // 64 threads, 16x16 output tile
    const dim3 dblk(8, 16);
    const int N = 32;

    // ---- Encoder ----
    // conv1: 3->64, k4 s2 p1, relu  (256 -> 128)
    conv2d_kernel<4, 2, 16, 4><<<dim3(8, 8, N * (64 / 16)), blk>>>(
        x, enc_w1, enc_b1, nullptr, b1, 3, 256, 256, 64, 128, 128, 1, 0, 1);
    // conv2: 64->128, k4 s2 p1, relu  (128 -> 64)
    conv2d_kernel<4, 2, 16, 4><<<dim3(4, 4, N * (128 / 16)), blk>>>(
        b1, enc_w2, enc_b2, nullptr, b2, 64, 128, 128, 128, 64, 64, 1, 0, 1);
    // conv3: 128->128, k3 s1 p1, no act
    conv2d_kernel<3, 1, 16, 8><<<dim3(4, 4, N * (128 / 16)), blk>>>(
        b2, enc_w3, enc_b3, nullptr, b3, 128, 64, 64, 128, 64, 64, 1, 0, 0);
    // residual stack x2 (3x3 at OCB=8)
    for (int i = 0; i < 2; i++) {
        const float* w1p = enc_rw1 + (size_t)i * 32 * 128 * 9;
        const float* b1p = enc_rb1 + i * 32;
        const float* w2p = enc_rw2 + (size_t)i * 128 * 32;
        const float* b2p = enc_rb2 + i * 128;
        conv2d_kernel<3, 1, 8, 8><<<dim3(4, 4, N * (32 / 8)), blk>>>(
            b3, w1p, b1p, nullptr, b4, 128, 64, 64, 32, 64, 64, 1, 1, 0);
        conv2d_kernel<1, 1, 16, 16><<<dim3(4, 4, N * (128 / 16)), blk>>>(
            b4, w2p, b2p, b3, b3, 32, 64, 64, 128, 64, 64, 0, 1, (i == 1) ? 1 : 0);
    }
    // pre-VQ 1x1: 128->64
    conv2d_kernel<1, 1, 16, 16><<<dim3(4, 4, N * (64 / 16)), blk>>>(
        b3, pvq_w, pvq_b, nullptr, bz, 128, 64, 64, 64, 64, 64, 0, 0, 0);

    // ---- VQ ----
    vq_prep_kernel<<<2, 256>>>(codebook, pe);
    vq_kernel<<<1024, 128>>>(bz, codebook, pe, bq, pbs);

    // ---- Decoder ----
    // dec conv1: 64->128, k3 s1 p1, no act
    conv2d_kernel<3, 1, 16, 8><<<dim3(4, 4, N * (128 / 16)), blk>>>(
        bq, dec_w1, dec_b1, nullptr, bd, 64, 64, 64, 128, 64, 64, 1, 0, 0);
    // residual stack x2
    for (int i = 0; i < 2; i++) {
        const float* w1p = dec_rw1 + (size_t)i * 32 * 128 * 9;
        const float* b1p = dec_rb1 + i * 32;
        const float* w2p = dec_rw2 + (size_t)i * 128 * 32;
        const float* b2p = dec_rb2 + i * 128;
        conv2d_kernel<3, 1, 8, 8><<<dim3(4, 4, N * (32 / 8)), blk>>>(
            bd, w1p, b1p, nullptr, b4, 128, 64, 64, 32, 64, 64, 1, 1, 0);
        conv2d_kernel<1, 1, 16, 16><<<dim3(4, 4, N * (128 / 16)), blk>>>(
            b4, w2p, b2p, bd, bd, 32, 64, 64, 128, 64, 64, 0, 1, (i == 1) ? 1 : 0);
    }
    // deconv1: 128->64, relu  (64 -> 128) — async variant (input bd already
    // post-relu from the last dec 1x1; single buffer, no dataflow change)
    deconv_k4s2_async_kernel<8, 8><<<dim3(4, 4, N * (64 / 8)), dblk>>>(
        bd, dt1_w, dt1_b, b1, 128, 64, 64, 64, 1);
    // deconv2: 64->3, tanh  (128 -> 256), COB=4 generic
    deconv_k4s2_kernel<4, 8><<<dim3(8, 8, N * 1), dblk>>>(
        b1, dt2_w, dt2_b, outp, 64, 128, 128, 3, 2);

    // vq_loss -> last output element (deterministic fixed-order reduction)
    finalize_kernel<<<1, 256>>>(pbs, outp + (out_size - 1));
}